// round 10
// baseline (speedup 1.0000x reference)
#include <cuda_runtime.h>

// Problem constants
#define S_STEPS 15
#define NETW 16
#define NCH 16
#define HW 4096            // 64*64
#define NPIX (64 * 4096)   // B*H*W = 262144
#define NTHREADS (NPIX / 4)  // 65536: four pixels per thread (2x f32x2 pairs)
#define TPB 128
#define HALF_LOG_2PI 0.918938533204672741780329736406f

typedef unsigned long long ull;

union F2U { ull u; float2 f; };
__device__ __forceinline__ ull f2u(float2 f) { F2U t; t.f = f; return t.u; }
__device__ __forceinline__ float2 u2f(ull u) { F2U t; t.u = u; return t.f; }

// Packed dual-FMA: 2 fp32 FMAs per instruction on the fma pipe (sm_10x).
__device__ __forceinline__ ull ffma2(ull a, ull b, ull c) {
    ull d;
    asm("fma.rn.f32x2 %0, %1, %2, %3;" : "=l"(d) : "l"(a), "l"(b), "l"(c));
    return d;
}

__device__ __forceinline__ ull relu2(ull a) {
    float2 f = u2f(a);
    return f2u(make_float2(fmaxf(f.x, 0.f), fmaxf(f.y, 0.f)));
}

// One LDS.128 wavefront -> two independent 64-bit packed weights.
// Destinations are plain 64-bit values consumed immediately, so ptxas keeps
// full freedom on register placement (no struct copies like ulonglong2).
__device__ __forceinline__ void lds_pair(const float2* p, ull& a, ull& b) {
    unsigned addr = (unsigned)__cvta_generic_to_shared(p);
    asm("ld.shared.v2.u64 {%0, %1}, [%2];" : "=l"(a), "=l"(b) : "r"(addr));
}

// Launch-constant parameters of the first-channel head (input is zeros):
// [0] = loc1, [1] = exp(-log_scale1), [2] = -log_scale1 - 0.5*log(2*pi)
__device__ float g_c1[3];

__global__ void precompute_kernel(const float* __restrict__ n1_b1,
                                  const float* __restrict__ n1_w2,
                                  const float* __restrict__ n1_b2,
                                  const float* __restrict__ n1_w3,
                                  const float* __restrict__ n1_b3) {
    if (threadIdx.x == 0) {
        float h1[NETW], h2[NETW];
        #pragma unroll
        for (int i = 0; i < NETW; i++) h1[i] = fmaxf(n1_b1[i], 0.f);
        #pragma unroll
        for (int o = 0; o < NETW; o++) {
            float a = n1_b2[o];
            #pragma unroll
            for (int p = 0; p < NETW; p++) a += n1_w2[o * NETW + p] * h1[p];
            h2[o] = fmaxf(a, 0.f);
        }
        float loc = n1_b3[0], ls = n1_b3[1];
        #pragma unroll
        for (int p = 0; p < NETW; p++) {
            loc += n1_w3[p] * h2[p];
            ls  += n1_w3[NETW + p] * h2[p];
        }
        g_c1[0] = loc;
        g_c1[1] = expf(-ls);
        g_c1[2] = -ls - HALF_LOG_2PI;
    }
}

// Shared memory layout (units = float2; weights duplicated (w,w) so the FFMA2
// multiplier operand comes straight from shared with no pack MOV). 16-byte
// alignment of every even element holds because all row strides are even.
#define SW1_OFF 0
#define SW2_OFF (S_STEPS * 256)
#define SW3_OFF (2 * S_STEPS * 256)
#define SB1_OFF (SW3_OFF + S_STEPS * 32)
#define SB2_OFF (SB1_OFF + S_STEPS * 16)
#define SB3_OFF (SB2_OFF + S_STEPS * 16)
#define SM_F2_TOT (SB3_OFF + S_STEPS * 2)
#define SM_BYTES (SM_F2_TOT * 8)   // 69360 bytes -> 3 CTAs/SM (208KB)

// One autoregressive step applied to TWO pixel-pairs (a,b) sharing every
// weight load. CLIM = live input channels for layer 1 (triangular mask:
// w1[s,:,c]=0 for c>s). All shared reads are paired (LDS.128).
template<int CLIM>
__device__ __forceinline__ void do_step(
    const float2* __restrict__ w1p, const float2* __restrict__ w2p,
    const float2* __restrict__ w3p, const float2* __restrict__ b1p,
    const float2* __restrict__ b2p, const float2* __restrict__ b3p,
    const ull* __restrict__ xa, const ull* __restrict__ xb,
    ull xsa, ull xsb, float2& lpa, float2& lpb) {

    ull h1a[NETW], h1b[NETW];
    #pragma unroll
    for (int q = 0; q < 8; q++) {
        lds_pair(b1p + 2 * q, h1a[2 * q], h1a[2 * q + 1]);
        h1b[2 * q] = h1a[2 * q];
        h1b[2 * q + 1] = h1a[2 * q + 1];
    }
    #pragma unroll
    for (int o = 0; o < NETW; o++) {
        ull acc_a = h1a[o];
        ull acc_b = h1b[o];
        #pragma unroll
        for (int c = 0; c < CLIM; c += 2) {
            ull w0, w1v;
            lds_pair(w1p + o * NCH + c, w0, w1v);
            acc_a = ffma2(w0, xa[c], acc_a);
            acc_b = ffma2(w0, xb[c], acc_b);
            acc_a = ffma2(w1v, xa[c + 1], acc_a);
            acc_b = ffma2(w1v, xb[c + 1], acc_b);
        }
        h1a[o] = relu2(acc_a);
        h1b[o] = relu2(acc_b);
    }

    ull h2a[NETW], h2b[NETW];
    #pragma unroll
    for (int q = 0; q < 8; q++) {
        lds_pair(b2p + 2 * q, h2a[2 * q], h2a[2 * q + 1]);
        h2b[2 * q] = h2a[2 * q];
        h2b[2 * q + 1] = h2a[2 * q + 1];
    }
    #pragma unroll
    for (int o = 0; o < NETW; o++) {
        ull acc_a = h2a[o];
        ull acc_b = h2b[o];
        #pragma unroll
        for (int p = 0; p < NETW; p += 2) {
            ull w0, w1v;
            lds_pair(w2p + o * NETW + p, w0, w1v);
            acc_a = ffma2(w0, h1a[p], acc_a);
            acc_b = ffma2(w0, h1b[p], acc_b);
            acc_a = ffma2(w1v, h1a[p + 1], acc_a);
            acc_b = ffma2(w1v, h1b[p + 1], acc_b);
        }
        h2a[o] = relu2(acc_a);
        h2b[o] = relu2(acc_b);
    }

    ull accLa, accLb, accSa, accSb;
    lds_pair(b3p, accLa, accSa);
    accLb = accLa;
    accSb = accSa;
    #pragma unroll
    for (int p = 0; p < NETW; p += 2) {
        ull wl0, wl1;
        lds_pair(w3p + p, wl0, wl1);
        accLa = ffma2(wl0, h2a[p], accLa);
        accLb = ffma2(wl0, h2b[p], accLb);
        accLa = ffma2(wl1, h2a[p + 1], accLa);
        accLb = ffma2(wl1, h2b[p + 1], accLb);
        ull ws0, ws1;
        lds_pair(w3p + NETW + p, ws0, ws1);
        accSa = ffma2(ws0, h2a[p], accSa);
        accSb = ffma2(ws0, h2b[p], accSb);
        accSa = ffma2(ws1, h2a[p + 1], accSa);
        accSb = ffma2(ws1, h2b[p + 1], accSb);
    }

    {
        float2 loc = u2f(accLa), ls = u2f(accSa), x = u2f(xsa);
        float za = (x.x - loc.x) * __expf(-ls.x);
        float zb = (x.y - loc.y) * __expf(-ls.y);
        lpa.x += -0.5f * za * za - ls.x - HALF_LOG_2PI;
        lpa.y += -0.5f * zb * zb - ls.y - HALF_LOG_2PI;
    }
    {
        float2 loc = u2f(accLb), ls = u2f(accSb), x = u2f(xsb);
        float za = (x.x - loc.x) * __expf(-ls.x);
        float zb = (x.y - loc.y) * __expf(-ls.y);
        lpb.x += -0.5f * za * za - ls.x - HALF_LOG_2PI;
        lpb.y += -0.5f * zb * zb - ls.y - HALF_LOG_2PI;
    }
}

__global__ __launch_bounds__(TPB, 3) void spatial_nn_kernel(
    const float* __restrict__ samples,
    const float* __restrict__ w1, const float* __restrict__ b1,
    const float* __restrict__ w2, const float* __restrict__ b2,
    const float* __restrict__ w3, const float* __restrict__ b3,
    float* __restrict__ out) {
    extern __shared__ float2 sm[];
    const int tid = threadIdx.x;

    // Stage duplicated weights into shared memory (broadcast reads later).
    for (int i = tid; i < S_STEPS * 256; i += TPB) { float v = w1[i]; sm[SW1_OFF + i] = make_float2(v, v); }
    for (int i = tid; i < S_STEPS * 256; i += TPB) { float v = w2[i]; sm[SW2_OFF + i] = make_float2(v, v); }
    for (int i = tid; i < S_STEPS * 32;  i += TPB) { float v = w3[i]; sm[SW3_OFF + i] = make_float2(v, v); }
    for (int i = tid; i < S_STEPS * 16;  i += TPB) { float v = b1[i]; sm[SB1_OFF + i] = make_float2(v, v); }
    for (int i = tid; i < S_STEPS * 16;  i += TPB) { float v = b2[i]; sm[SB2_OFF + i] = make_float2(v, v); }
    for (int i = tid; i < S_STEPS * 2;   i += TPB) { float v = b3[i]; sm[SB3_OFF + i] = make_float2(v, v); }
    __syncthreads();

    const int t = blockIdx.x * TPB + tid;
    const int pix = t * 4;                  // first of 4 adjacent pixels
    const int b = pix >> 12;                // / (H*W)
    const int hw = pix & 4095;              // % (H*W)
    const float* sp = samples + ((size_t)b * NCH) * HW + hw;

    // Load all 16 channels for 4 pixels: one float4 per channel, split into
    // two f32x2 packs (pair a = pixels 0,1; pair b = pixels 2,3).
    ull xa[NCH], xb[NCH];
    #pragma unroll
    for (int c = 0; c < NCH; c++) {
        float4 v = *reinterpret_cast<const float4*>(sp + c * HW);
        xa[c] = f2u(make_float2(v.x, v.y));
        xb[c] = f2u(make_float2(v.z, v.w));
    }

    // First-channel log-prob from the precomputed constants.
    const float loc1 = g_c1[0], inv1 = g_c1[1], c1 = g_c1[2];
    float2 lpa, lpb;
    {
        float2 x0 = u2f(xa[0]);
        float z0 = (x0.x - loc1) * inv1;
        float z1 = (x0.y - loc1) * inv1;
        lpa = make_float2(-0.5f * z0 * z0 + c1, -0.5f * z1 * z1 + c1);
        float2 x1 = u2f(xb[0]);
        float z2 = (x1.x - loc1) * inv1;
        float z3 = (x1.y - loc1) * inv1;
        lpb = make_float2(-0.5f * z2 * z2 + c1, -0.5f * z3 * z3 + c1);
    }

    // Fine triangular split: CLIM grows with the step group.
    #pragma unroll 1
    for (int s = 0; s < 4; s++) {
        do_step<4>(sm + SW1_OFF + s * 256, sm + SW2_OFF + s * 256,
                   sm + SW3_OFF + s * 32, sm + SB1_OFF + s * 16,
                   sm + SB2_OFF + s * 16, sm + SB3_OFF + s * 2,
                   xa, xb, xa[s + 1], xb[s + 1], lpa, lpb);
    }
    #pragma unroll 1
    for (int s = 4; s < 8; s++) {
        do_step<8>(sm + SW1_OFF + s * 256, sm + SW2_OFF + s * 256,
                   sm + SW3_OFF + s * 32, sm + SB1_OFF + s * 16,
                   sm + SB2_OFF + s * 16, sm + SB3_OFF + s * 2,
                   xa, xb, xa[s + 1], xb[s + 1], lpa, lpb);
    }
    #pragma unroll 1
    for (int s = 8; s < 12; s++) {
        do_step<12>(sm + SW1_OFF + s * 256, sm + SW2_OFF + s * 256,
                    sm + SW3_OFF + s * 32, sm + SB1_OFF + s * 16,
                    sm + SB2_OFF + s * 16, sm + SB3_OFF + s * 2,
                    xa, xb, xa[s + 1], xb[s + 1], lpa, lpb);
    }
    #pragma unroll 1
    for (int s = 12; s < S_STEPS; s++) {
        do_step<16>(sm + SW1_OFF + s * 256, sm + SW2_OFF + s * 256,
                    sm + SW3_OFF + s * 32, sm + SB1_OFF + s * 16,
                    sm + SB2_OFF + s * 16, sm + SB3_OFF + s * 2,
                    xa, xb, xa[s + 1], xb[s + 1], lpa, lpb);
    }

    *reinterpret_cast<float4*>(out + pix) =
        make_float4(lpa.x, lpa.y, lpb.x, lpb.y);
}

extern "C" void kernel_launch(void* const* d_in, const int* in_sizes, int n_in,
                              void* d_out, int out_size) {
    const float* samples = (const float*)d_in[0];
    // d_in[1] = n1_w1 (unused: multiplies a zeros input)
    const float* n1_b1 = (const float*)d_in[2];
    const float* n1_w2 = (const float*)d_in[3];
    const float* n1_b2 = (const float*)d_in[4];
    const float* n1_w3 = (const float*)d_in[5];
    const float* n1_b3 = (const float*)d_in[6];
    const float* w1 = (const float*)d_in[7];
    const float* b1 = (const float*)d_in[8];
    const float* w2 = (const float*)d_in[9];
    const float* b2 = (const float*)d_in[10];
    const float* w3 = (const float*)d_in[11];
    const float* b3 = (const float*)d_in[12];
    float* out = (float*)d_out;

    // Opt in to >48KB dynamic shared memory (idempotent; skip if already set
    // so the graph-capture call performs no attribute mutation).
    cudaFuncAttributes attr;
    cudaFuncGetAttributes(&attr, spatial_nn_kernel);
    if (attr.maxDynamicSharedSizeBytes < SM_BYTES) {
        cudaFuncSetAttribute(spatial_nn_kernel,
                             cudaFuncAttributeMaxDynamicSharedMemorySize, SM_BYTES);
    }

    precompute_kernel<<<1, 32>>>(n1_b1, n1_w2, n1_b2, n1_w3, n1_b3);
    spatial_nn_kernel<<<NTHREADS / TPB, TPB, SM_BYTES>>>(
        samples, w1, b1, w2, b2, w3, b3, out);
}

// round 13
// speedup vs baseline: 1.9864x; 1.9864x over previous
#include <cuda_runtime.h>
#include <cuda_bf16.h>
#include <cstdint>

// Problem constants
#define S_STEPS 15
#define HW 4096
#define NPIX (64 * 4096)
#define NT_TILES 16384        // NPIX / 16 pixels per warp-tile
#define TPB 128
#define GRID 1024             // 4096 warps -> 4 tiles per warp
#define HALF_LOG_2PI 0.918938533204672741780329736406f

typedef unsigned long long ull;

// ---------------- precomputed fragment tables (built on device) -------------
// B-fragment for mma.sync.m16n8k16.row.col, K=16 inputs, N=8 outputs:
//   lane (gid=lane>>2, tig=lane&3) holds
//     b0 = { W[n][2tig],   W[n][2tig+1] }   (n = gid + 8*half)
//     b1 = { W[n][2tig+8], W[n][2tig+9] }
// packed bf16x2, stored as one ull (lo=b0, hi=b1) per lane.
struct Tables {
    ull    b1frag[S_STEPS][2][32];
    ull    b2frag[S_STEPS][2][32];
    float2 b1pair[S_STEPS][8];    // (b1[2j], b1[2j+1])
    float2 b2pair[S_STEPS][8];
    float2 w3loc[S_STEPS][8];     // (w3[s][0][2j], w3[s][0][2j+1])
    float2 w3ls[S_STEPS][8];      // (w3[s][1][2j], w3[s][1][2j+1])
    float2 b3v[S_STEPS];          // (b3[s][0], b3[s][1])
};
__device__ Tables g_tab;
__device__ float g_c1[3];   // loc1, exp(-ls1), -ls1 - 0.5*log(2pi)

__device__ __forceinline__ uint32_t packbf(float lo, float hi) {
    __nv_bfloat162 t = __floats2bfloat162_rn(lo, hi);
    return *reinterpret_cast<uint32_t*>(&t);
}

__global__ void precompute_kernel(
    const float* __restrict__ n1_b1, const float* __restrict__ n1_w2,
    const float* __restrict__ n1_b2, const float* __restrict__ n1_w3,
    const float* __restrict__ n1_b3,
    const float* __restrict__ w1, const float* __restrict__ b1,
    const float* __restrict__ w2, const float* __restrict__ b2,
    const float* __restrict__ w3, const float* __restrict__ b3) {
    const int tid = threadIdx.x;

    // B fragments for W1 / W2
    for (int idx = tid; idx < S_STEPS * 2 * 32; idx += blockDim.x) {
        int s = idx >> 6, rem = idx & 63, h = rem >> 5, l = rem & 31;
        int gid = l >> 2, tig = l & 3;
        int n = gid + 8 * h;
        int k0 = 2 * tig;
        const float* w1r = w1 + (s * 16 + n) * 16;
        const float* w2r = w2 + (s * 16 + n) * 16;
        uint32_t lo1 = packbf(w1r[k0], w1r[k0 + 1]);
        uint32_t hi1 = packbf(w1r[k0 + 8], w1r[k0 + 9]);
        uint32_t lo2 = packbf(w2r[k0], w2r[k0 + 1]);
        uint32_t hi2 = packbf(w2r[k0 + 8], w2r[k0 + 9]);
        g_tab.b1frag[s][h][l] = (ull)lo1 | ((ull)hi1 << 32);
        g_tab.b2frag[s][h][l] = (ull)lo2 | ((ull)hi2 << 32);
    }
    // bias pairs + layer-3 head
    for (int idx = tid; idx < S_STEPS * 8; idx += blockDim.x) {
        int s = idx >> 3, j = idx & 7;
        g_tab.b1pair[s][j] = make_float2(b1[s * 16 + 2 * j], b1[s * 16 + 2 * j + 1]);
        g_tab.b2pair[s][j] = make_float2(b2[s * 16 + 2 * j], b2[s * 16 + 2 * j + 1]);
        g_tab.w3loc[s][j] = make_float2(w3[s * 32 + 2 * j], w3[s * 32 + 2 * j + 1]);
        g_tab.w3ls[s][j]  = make_float2(w3[s * 32 + 16 + 2 * j], w3[s * 32 + 16 + 2 * j + 1]);
    }
    for (int s = tid; s < S_STEPS; s += blockDim.x)
        g_tab.b3v[s] = make_float2(b3[2 * s], b3[2 * s + 1]);

    // first-channel head (input is zeros -> launch constant)
    if (tid == 0) {
        float h1[16], h2[16];
        #pragma unroll
        for (int i = 0; i < 16; i++) h1[i] = fmaxf(n1_b1[i], 0.f);
        #pragma unroll
        for (int o = 0; o < 16; o++) {
            float a = n1_b2[o];
            #pragma unroll
            for (int p = 0; p < 16; p++) a += n1_w2[o * 16 + p] * h1[p];
            h2[o] = fmaxf(a, 0.f);
        }
        float loc = n1_b3[0], ls = n1_b3[1];
        #pragma unroll
        for (int p = 0; p < 16; p++) {
            loc += n1_w3[p] * h2[p];
            ls  += n1_w3[16 + p] * h2[p];
        }
        g_c1[0] = loc;
        g_c1[1] = expf(-ls);
        g_c1[2] = -ls - HALF_LOG_2PI;
    }
}

// m16n8k16 bf16 MMA, C accumulated in place (bias pre-loaded into d0..d3).
__device__ __forceinline__ void mma16816(
    float& d0, float& d1, float& d2, float& d3,
    uint32_t a0, uint32_t a1, uint32_t a2, uint32_t a3,
    uint32_t b0, uint32_t b1) {
    asm("mma.sync.aligned.m16n8k16.row.col.f32.bf16.bf16.f32 "
        "{%0,%1,%2,%3}, {%4,%5,%6,%7}, {%8,%9}, {%0,%1,%2,%3};"
        : "+f"(d0), "+f"(d1), "+f"(d2), "+f"(d3)
        : "r"(a0), "r"(a1), "r"(a2), "r"(a3), "r"(b0), "r"(b1));
}

#define SM_BYTES ((int)sizeof(Tables))

__global__ __launch_bounds__(TPB) void spatial_mma_kernel(
    const float* __restrict__ samples, float* __restrict__ out) {
    extern __shared__ char smem[];
    Tables* tab = reinterpret_cast<Tables*>(smem);
    const int tid = threadIdx.x;
    const int lane = tid & 31;
    const int wid = tid >> 5;
    const int gid = lane >> 2;    // 0..7  : D/A row group
    const int tig = lane & 3;     // 0..3  : column group

    // Stage the fragment tables into shared memory (coalesced ull copy).
    {
        const ull* src = reinterpret_cast<const ull*>(&g_tab);
        ull* dst = reinterpret_cast<ull*>(smem);
        for (int i = tid; i < SM_BYTES / 8; i += TPB) dst[i] = src[i];
    }
    __syncthreads();

    const float loc1 = g_c1[0], inv1 = g_c1[1], c1 = g_c1[2];
    const int gw = blockIdx.x * (TPB / 32) + wid;    // global warp id

    for (int tile = gw; tile < NT_TILES; tile += GRID * (TPB / 32)) {
        const int pixb = tile * 16;
        const int b = pixb >> 12;
        const int hw = pixb & 4095;
        const float* base = samples + ((size_t)b * 16) * HW + hw;

        // x (f32, exact) for this thread's fragment channels, both rows.
        // channels: 2tig, 2tig+1, 2tig+8, 2tig+9 ; rows gid, gid+8.
        float xr0[4], xr1[4];
        {
            const int c0 = 2 * tig, c2 = 2 * tig + 8;
            xr0[0] = base[c0 * HW + gid];       xr0[1] = base[(c0 + 1) * HW + gid];
            xr0[2] = base[c2 * HW + gid];       xr0[3] = base[(c2 + 1) * HW + gid];
            xr1[0] = base[c0 * HW + gid + 8];   xr1[1] = base[(c0 + 1) * HW + gid + 8];
            xr1[2] = base[c2 * HW + gid + 8];   xr1[3] = base[(c2 + 1) * HW + gid + 8];
        }

        // A fragment of X (bf16).
        uint32_t ax0 = packbf(xr0[0], xr0[1]);
        uint32_t ax1 = packbf(xr1[0], xr1[1]);
        uint32_t ax2 = packbf(xr0[2], xr0[3]);
        uint32_t ax3 = packbf(xr1[2], xr1[3]);

        // First-channel log-prob (x[0] lives at tig==0, reg xr*[0]).
        const int qbase = lane & ~3;
        float x00 = __shfl_sync(0xffffffffu, xr0[0], qbase);
        float x01 = __shfl_sync(0xffffffffu, xr1[0], qbase);
        float z0i = (x00 - loc1) * inv1;
        float z1i = (x01 - loc1) * inv1;
        float lp0 = -0.5f * z0i * z0i + c1;
        float lp1 = -0.5f * z1i * z1i + c1;

        #pragma unroll
        for (int s = 0; s < S_STEPS; s++) {
            // ---- layer 1: two n-halves, bias in C ----
            float2 bp = tab->b1pair[s][tig];
            float2 bq = tab->b1pair[s][tig + 4];
            float d0 = bp.x, d1 = bp.y, d2 = bp.x, d3 = bp.y;
            float e0 = bq.x, e1 = bq.y, e2 = bq.x, e3 = bq.y;
            {
                ull bb = tab->b1frag[s][0][lane];
                mma16816(d0, d1, d2, d3, ax0, ax1, ax2, ax3,
                         (uint32_t)bb, (uint32_t)(bb >> 32));
                ull bc = tab->b1frag[s][1][lane];
                mma16816(e0, e1, e2, e3, ax0, ax1, ax2, ax3,
                         (uint32_t)bc, (uint32_t)(bc >> 32));
            }
            d0 = fmaxf(d0, 0.f); d1 = fmaxf(d1, 0.f); d2 = fmaxf(d2, 0.f); d3 = fmaxf(d3, 0.f);
            e0 = fmaxf(e0, 0.f); e1 = fmaxf(e1, 0.f); e2 = fmaxf(e2, 0.f); e3 = fmaxf(e3, 0.f);

            // D layout == A layout: repack relu'd h1 directly as layer-2 A.
            uint32_t a10 = packbf(d0, d1);
            uint32_t a11 = packbf(d2, d3);
            uint32_t a12 = packbf(e0, e1);
            uint32_t a13 = packbf(e2, e3);

            // ---- layer 2 ----
            float2 cp = tab->b2pair[s][tig];
            float2 cq = tab->b2pair[s][tig + 4];
            float f0 = cp.x, f1 = cp.y, f2 = cp.x, f3 = cp.y;
            float g0 = cq.x, g1 = cq.y, g2 = cq.x, g3 = cq.y;
            {
                ull bb = tab->b2frag[s][0][lane];
                mma16816(f0, f1, f2, f3, a10, a11, a12, a13,
                         (uint32_t)bb, (uint32_t)(bb >> 32));
                ull bc = tab->b2frag[s][1][lane];
                mma16816(g0, g1, g2, g3, a10, a11, a12, a13,
                         (uint32_t)bc, (uint32_t)(bc >> 32));
            }
            f0 = fmaxf(f0, 0.f); f1 = fmaxf(f1, 0.f); f2 = fmaxf(f2, 0.f); f3 = fmaxf(f3, 0.f);
            g0 = fmaxf(g0, 0.f); g1 = fmaxf(g1, 0.f); g2 = fmaxf(g2, 0.f); g3 = fmaxf(g3, 0.f);

            // ---- layer 3 partials over this thread's 4 h2 columns ----
            float2 wl = tab->w3loc[s][tig];
            float2 wl2 = tab->w3loc[s][tig + 4];
            float2 ws = tab->w3ls[s][tig];
            float2 ws2 = tab->w3ls[s][tig + 4];
            float locA = wl.x * f0 + wl.y * f1 + wl2.x * g0 + wl2.y * g1;
            float lsA  = ws.x * f0 + ws.y * f1 + ws2.x * g0 + ws2.y * g1;
            float locB = wl.x * f2 + wl.y * f3 + wl2.x * g2 + wl2.y * g3;
            float lsB  = ws.x * f2 + ws.y * f3 + ws2.x * g2 + ws2.y * g3;

            // quad reduction (tig 0..3 cover all 16 k)
            locA += __shfl_xor_sync(0xffffffffu, locA, 1);
            lsA  += __shfl_xor_sync(0xffffffffu, lsA, 1);
            locB += __shfl_xor_sync(0xffffffffu, locB, 1);
            lsB  += __shfl_xor_sync(0xffffffffu, lsB, 1);
            locA += __shfl_xor_sync(0xffffffffu, locA, 2);
            lsA  += __shfl_xor_sync(0xffffffffu, lsA, 2);
            locB += __shfl_xor_sync(0xffffffffu, locB, 2);
            lsB  += __shfl_xor_sync(0xffffffffu, lsB, 2);

            float2 b3p = tab->b3v[s];
            locA += b3p.x; lsA += b3p.y;
            locB += b3p.x; lsB += b3p.y;

            // target x[s+1] (exact f32) via static shuffle from its owner
            const int ch = s + 1;
            const int tig_o = (ch & 7) >> 1;
            const int ridx = ((ch >= 8) ? 2 : 0) + (ch & 1);
            float xs0 = __shfl_sync(0xffffffffu, xr0[ridx], qbase | tig_o);
            float xs1 = __shfl_sync(0xffffffffu, xr1[ridx], qbase | tig_o);

            float za = (xs0 - locA) * __expf(-lsA);
            float zb = (xs1 - locB) * __expf(-lsB);
            lp0 += -0.5f * za * za - lsA - HALF_LOG_2PI;
            lp1 += -0.5f * zb * zb - lsB - HALF_LOG_2PI;
        }

        if (tig == 0) {
            out[pixb + gid] = lp0;
            out[pixb + gid + 8] = lp1;
        }
    }
}

extern "C" void kernel_launch(void* const* d_in, const int* in_sizes, int n_in,
                              void* d_out, int out_size) {
    const float* samples = (const float*)d_in[0];
    // d_in[1] = n1_w1 (unused: multiplies a zeros input)
    const float* n1_b1 = (const float*)d_in[2];
    const float* n1_w2 = (const float*)d_in[3];
    const float* n1_b2 = (const float*)d_in[4];
    const float* n1_w3 = (const float*)d_in[5];
    const float* n1_b3 = (const float*)d_in[6];
    const float* w1 = (const float*)d_in[7];
    const float* b1 = (const float*)d_in[8];
    const float* w2 = (const float*)d_in[9];
    const float* b2 = (const float*)d_in[10];
    const float* w3 = (const float*)d_in[11];
    const float* b3 = (const float*)d_in[12];
    float* out = (float*)d_out;

    precompute_kernel<<<1, 256>>>(n1_b1, n1_w2, n1_b2, n1_w3, n1_b3,
                                  w1, b1, w2, b2, w3, b3);
    spatial_mma_kernel<<<GRID, TPB, SM_BYTES>>>(samples, out);
}

// round 14
// speedup vs baseline: 2.0773x; 1.0457x over previous
#include <cuda_runtime.h>
#include <cuda_bf16.h>
#include <cstdint>

// Problem constants
#define S_STEPS 15
#define HW 4096
#define NPIX (64 * 4096)
#define NT_TILES 16384        // NPIX / 16 pixels per warp-tile
#define TPB 128
#define GRID 4096             // 16384 warps -> exactly 1 tile per warp
#define HALF_LOG_2PI 0.918938533204672741780329736406f

typedef unsigned long long ull;

// ---------------- precomputed fragment tables (built on device) -------------
// B-fragment for mma.sync.m16n8k16.row.col, K=16 inputs, N=8 outputs:
//   lane (gid=lane>>2, tig=lane&3) holds
//     b0 = { W[n][2tig],   W[n][2tig+1] }   (n = gid + 8*half)
//     b1 = { W[n][2tig+8], W[n][2tig+9] }
// packed bf16x2, stored as one ull (lo=b0, hi=b1) per lane.
struct Tables {
    ull    b1frag[S_STEPS][2][32];
    ull    b2frag[S_STEPS][2][32];
    float2 b1pair[S_STEPS][8];    // (b1[2j], b1[2j+1])
    float2 b2pair[S_STEPS][8];
    float2 w3loc[S_STEPS][8];     // (w3[s][0][2j], w3[s][0][2j+1])
    float2 w3ls[S_STEPS][8];      // (w3[s][1][2j], w3[s][1][2j+1])
    float2 b3v[S_STEPS];          // (b3[s][0], b3[s][1])
};
__device__ Tables g_tab;
__device__ float g_c1[3];   // loc1, exp(-ls1), -ls1 - 0.5*log(2pi)

__device__ __forceinline__ uint32_t packbf(float lo, float hi) {
    __nv_bfloat162 t = __floats2bfloat162_rn(lo, hi);
    return *reinterpret_cast<uint32_t*>(&t);
}

// relu on a packed bf16x2 (max against +0 in both halves)
__device__ __forceinline__ uint32_t relubf2(uint32_t v) {
    uint32_t r;
    asm("max.bf16x2 %0, %1, %2;" : "=r"(r) : "r"(v), "r"(0u));
    return r;
}

__global__ void precompute_kernel(
    const float* __restrict__ n1_b1, const float* __restrict__ n1_w2,
    const float* __restrict__ n1_b2, const float* __restrict__ n1_w3,
    const float* __restrict__ n1_b3,
    const float* __restrict__ w1, const float* __restrict__ b1,
    const float* __restrict__ w2, const float* __restrict__ b2,
    const float* __restrict__ w3, const float* __restrict__ b3) {
    const int tid = threadIdx.x;

    // B fragments for W1 / W2
    for (int idx = tid; idx < S_STEPS * 2 * 32; idx += blockDim.x) {
        int s = idx >> 6, rem = idx & 63, h = rem >> 5, l = rem & 31;
        int gid = l >> 2, tig = l & 3;
        int n = gid + 8 * h;
        int k0 = 2 * tig;
        const float* w1r = w1 + (s * 16 + n) * 16;
        const float* w2r = w2 + (s * 16 + n) * 16;
        uint32_t lo1 = packbf(w1r[k0], w1r[k0 + 1]);
        uint32_t hi1 = packbf(w1r[k0 + 8], w1r[k0 + 9]);
        uint32_t lo2 = packbf(w2r[k0], w2r[k0 + 1]);
        uint32_t hi2 = packbf(w2r[k0 + 8], w2r[k0 + 9]);
        g_tab.b1frag[s][h][l] = (ull)lo1 | ((ull)hi1 << 32);
        g_tab.b2frag[s][h][l] = (ull)lo2 | ((ull)hi2 << 32);
    }
    // bias pairs + layer-3 head
    for (int idx = tid; idx < S_STEPS * 8; idx += blockDim.x) {
        int s = idx >> 3, j = idx & 7;
        g_tab.b1pair[s][j] = make_float2(b1[s * 16 + 2 * j], b1[s * 16 + 2 * j + 1]);
        g_tab.b2pair[s][j] = make_float2(b2[s * 16 + 2 * j], b2[s * 16 + 2 * j + 1]);
        g_tab.w3loc[s][j] = make_float2(w3[s * 32 + 2 * j], w3[s * 32 + 2 * j + 1]);
        g_tab.w3ls[s][j]  = make_float2(w3[s * 32 + 16 + 2 * j], w3[s * 32 + 16 + 2 * j + 1]);
    }
    for (int s = tid; s < S_STEPS; s += blockDim.x)
        g_tab.b3v[s] = make_float2(b3[2 * s], b3[2 * s + 1]);

    // first-channel head (input is zeros -> launch constant)
    if (tid == 0) {
        float h1[16], h2[16];
        #pragma unroll
        for (int i = 0; i < 16; i++) h1[i] = fmaxf(n1_b1[i], 0.f);
        #pragma unroll
        for (int o = 0; o < 16; o++) {
            float a = n1_b2[o];
            #pragma unroll
            for (int p = 0; p < 16; p++) a += n1_w2[o * 16 + p] * h1[p];
            h2[o] = fmaxf(a, 0.f);
        }
        float loc = n1_b3[0], ls = n1_b3[1];
        #pragma unroll
        for (int p = 0; p < 16; p++) {
            loc += n1_w3[p] * h2[p];
            ls  += n1_w3[16 + p] * h2[p];
        }
        g_c1[0] = loc;
        g_c1[1] = expf(-ls);
        g_c1[2] = -ls - HALF_LOG_2PI;
    }
}

// m16n8k16 bf16 MMA, C accumulated in place (bias pre-loaded into d0..d3).
__device__ __forceinline__ void mma16816(
    float& d0, float& d1, float& d2, float& d3,
    uint32_t a0, uint32_t a1, uint32_t a2, uint32_t a3,
    uint32_t b0, uint32_t b1) {
    asm("mma.sync.aligned.m16n8k16.row.col.f32.bf16.bf16.f32 "
        "{%0,%1,%2,%3}, {%4,%5,%6,%7}, {%8,%9}, {%0,%1,%2,%3};"
        : "+f"(d0), "+f"(d1), "+f"(d2), "+f"(d3)
        : "r"(a0), "r"(a1), "r"(a2), "r"(a3), "r"(b0), "r"(b1));
}

#define SM_BYTES ((int)sizeof(Tables))

__global__ __launch_bounds__(TPB) void spatial_mma_kernel(
    const float* __restrict__ samples, float* __restrict__ out) {
    extern __shared__ char smem[];
    Tables* tab = reinterpret_cast<Tables*>(smem);
    const int tid = threadIdx.x;
    const int lane = tid & 31;
    const int wid = tid >> 5;
    const int gid = lane >> 2;    // 0..7  : D/A row group
    const int tig = lane & 3;     // 0..3  : column group

    // Stage the fragment tables into shared memory (coalesced ull copy).
    {
        const ull* src = reinterpret_cast<const ull*>(&g_tab);
        ull* dst = reinterpret_cast<ull*>(smem);
        for (int i = tid; i < SM_BYTES / 8; i += TPB) dst[i] = src[i];
    }
    __syncthreads();

    const float loc1 = g_c1[0], inv1 = g_c1[1], c1 = g_c1[2];
    const int gw = blockIdx.x * (TPB / 32) + wid;    // global warp id

    for (int tile = gw; tile < NT_TILES; tile += GRID * (TPB / 32)) {
        const int pixb = tile * 16;
        const int b = pixb >> 12;
        const int hw = pixb & 4095;
        const float* base = samples + ((size_t)b * 16) * HW + hw;

        // x (f32, exact) for this thread's fragment channels, both rows.
        // channels: 2tig, 2tig+1, 2tig+8, 2tig+9 ; rows gid, gid+8.
        float xr0[4], xr1[4];
        {
            const int c0 = 2 * tig, c2 = 2 * tig + 8;
            xr0[0] = base[c0 * HW + gid];       xr0[1] = base[(c0 + 1) * HW + gid];
            xr0[2] = base[c2 * HW + gid];       xr0[3] = base[(c2 + 1) * HW + gid];
            xr1[0] = base[c0 * HW + gid + 8];   xr1[1] = base[(c0 + 1) * HW + gid + 8];
            xr1[2] = base[c2 * HW + gid + 8];   xr1[3] = base[(c2 + 1) * HW + gid + 8];
        }

        // A fragment of X (bf16).
        uint32_t ax0 = packbf(xr0[0], xr0[1]);
        uint32_t ax1 = packbf(xr1[0], xr1[1]);
        uint32_t ax2 = packbf(xr0[2], xr0[3]);
        uint32_t ax3 = packbf(xr1[2], xr1[3]);

        // First-channel log-prob. lp lives on lane tig==0 (pixel gid) and
        // lane tig==2 (pixel gid+8); other lanes carry dead values.
        const int qbase = lane & ~3;
        float x00 = __shfl_sync(0xffffffffu, xr0[0], qbase);
        float x01 = __shfl_sync(0xffffffffu, xr1[0], qbase);
        float x0sel = (tig & 2) ? x01 : x00;
        float zi = (x0sel - loc1) * inv1;
        float lp = -0.5f * zi * zi + c1;

        #pragma unroll
        for (int s = 0; s < S_STEPS; s++) {
            // ---- layer 1: two n-halves, bias in C ----
            float2 bp = tab->b1pair[s][tig];
            float2 bq = tab->b1pair[s][tig + 4];
            float d0 = bp.x, d1 = bp.y, d2 = bp.x, d3 = bp.y;
            float e0 = bq.x, e1 = bq.y, e2 = bq.x, e3 = bq.y;
            {
                ull bb = tab->b1frag[s][0][lane];
                mma16816(d0, d1, d2, d3, ax0, ax1, ax2, ax3,
                         (uint32_t)bb, (uint32_t)(bb >> 32));
                ull bc = tab->b1frag[s][1][lane];
                mma16816(e0, e1, e2, e3, ax0, ax1, ax2, ax3,
                         (uint32_t)bc, (uint32_t)(bc >> 32));
            }
            // pack then relu in bf16x2 (identical numerics, 4 alu ops vs 16)
            uint32_t a10 = relubf2(packbf(d0, d1));
            uint32_t a11 = relubf2(packbf(d2, d3));
            uint32_t a12 = relubf2(packbf(e0, e1));
            uint32_t a13 = relubf2(packbf(e2, e3));

            // ---- layer 2 ----
            float2 cp = tab->b2pair[s][tig];
            float2 cq = tab->b2pair[s][tig + 4];
            float f0 = cp.x, f1 = cp.y, f2 = cp.x, f3 = cp.y;
            float g0 = cq.x, g1 = cq.y, g2 = cq.x, g3 = cq.y;
            {
                ull bb = tab->b2frag[s][0][lane];
                mma16816(f0, f1, f2, f3, a10, a11, a12, a13,
                         (uint32_t)bb, (uint32_t)(bb >> 32));
                ull bc = tab->b2frag[s][1][lane];
                mma16816(g0, g1, g2, g3, a10, a11, a12, a13,
                         (uint32_t)bc, (uint32_t)(bc >> 32));
            }
            f0 = fmaxf(f0, 0.f); f1 = fmaxf(f1, 0.f); f2 = fmaxf(f2, 0.f); f3 = fmaxf(f3, 0.f);
            g0 = fmaxf(g0, 0.f); g1 = fmaxf(g1, 0.f); g2 = fmaxf(g2, 0.f); g3 = fmaxf(g3, 0.f);

            // ---- layer 3 partials over this thread's 4 h2 columns ----
            float2 wl = tab->w3loc[s][tig];
            float2 wl2 = tab->w3loc[s][tig + 4];
            float2 ws = tab->w3ls[s][tig];
            float2 ws2 = tab->w3ls[s][tig + 4];
            float v0 = wl.x * f0 + wl.y * f1 + wl2.x * g0 + wl2.y * g1;  // locA part
            float v1 = ws.x * f0 + ws.y * f1 + ws2.x * g0 + ws2.y * g1;  // lsA part
            float v2 = wl.x * f2 + wl.y * f3 + wl2.x * g2 + wl2.y * g3;  // locB part
            float v3 = ws.x * f2 + ws.y * f3 + ws2.x * g2 + ws2.y * g3;  // lsB part

            // Scatter quad-reduction: 3 shuffles land the four totals on
            // lanes tig=0(locA) 1(lsA) 2(locB) 3(lsB).
            float s1 = __shfl_xor_sync(0xffffffffu, (tig & 1) ? v0 : v1, 1);
            float s2 = __shfl_xor_sync(0xffffffffu, (tig & 1) ? v2 : v3, 1);
            float A  = ((tig & 1) ? v1 : v0) + s1;
            float Bv = ((tig & 1) ? v3 : v2) + s2;
            float s3 = __shfl_xor_sync(0xffffffffu, (tig & 2) ? A : Bv, 2);
            float tot = ((tig & 2) ? Bv : A) + s3;

            float2 b3p = tab->b3v[s];
            tot += (tig & 1) ? b3p.y : b3p.x;
            // pair loc with ls on the loc-holding lanes (0 and 2)
            float ls_t = __shfl_xor_sync(0xffffffffu, tot, 1);

            // target x[s+1] (exact f32) from its owner lane
            const int ch = s + 1;
            const int tig_o = (ch & 7) >> 1;
            const int ridx = ((ch >= 8) ? 2 : 0) + (ch & 1);
            float xs0 = __shfl_sync(0xffffffffu, xr0[ridx], qbase | tig_o);
            float xs1 = __shfl_sync(0xffffffffu, xr1[ridx], qbase | tig_o);
            float xs = (tig & 2) ? xs1 : xs0;

            float z = (xs - tot) * __expf(-ls_t);
            lp += -0.5f * z * z - ls_t - HALF_LOG_2PI;   // valid on lanes 0,2
        }

        if ((tig & 1) == 0)
            out[pixb + gid + ((tig & 2) ? 8 : 0)] = lp;
    }
}

extern "C" void kernel_launch(void* const* d_in, const int* in_sizes, int n_in,
                              void* d_out, int out_size) {
    const float* samples = (const float*)d_in[0];
    // d_in[1] = n1_w1 (unused: multiplies a zeros input)
    const float* n1_b1 = (const float*)d_in[2];
    const float* n1_w2 = (const float*)d_in[3];
    const float* n1_b2 = (const float*)d_in[4];
    const float* n1_w3 = (const float*)d_in[5];
    const float* n1_b3 = (const float*)d_in[6];
    const float* w1 = (const float*)d_in[7];
    const float* b1 = (const float*)d_in[8];
    const float* w2 = (const float*)d_in[9];
    const float* b2 = (const float*)d_in[10];
    const float* w3 = (const float*)d_in[11];
    const float* b3 = (const float*)d_in[12];
    float* out = (float*)d_out;

    precompute_kernel<<<1, 256>>>(n1_b1, n1_w2, n1_b2, n1_w3, n1_b3,
                                  w1, b1, w2, b2, w3, b3);
    spatial_mma_kernel<<<GRID, TPB, SM_BYTES>>>(samples, out);
}

// round 16
// speedup vs baseline: 2.6190x; 1.2608x over previous
#include <cuda_runtime.h>
#include <cuda_bf16.h>
#include <cstdint>

// Problem constants
#define S_STEPS 15
#define HW 4096
#define NPIX (64 * 4096)
#define NT_TILES 16384        // NPIX / 16 pixels per warp-tile
#define TPB 128
#define GRID 4096             // 16384 warps -> exactly 1 tile per warp
#define HALF_LOG_2PI 0.918938533204672741780329736406f

typedef unsigned long long ull;

// ---------------- precomputed fragment tables (built on device) -------------
// B-fragment for mma.sync.m16n8k16.row.col (validated in R11/R13):
//   lane (gid=lane>>2, tig=lane&3), output n = gid + 8*half:
//     b0 = { W[n][2tig],   W[n][2tig+1] },  b1 = { W[n][2tig+8], W[n][2tig+9] }
// b1frag/b2frag store both halves per lane as ulonglong2 (one LDS.128).
// w3frag: layer-3 B fragment, half 0 only (n=0 -> loc row, n=1 -> ls row,
// n>=2 -> zeros).  b1quad/b2quad: per-tig bias float4 (b[2t],b[2t+1],
// b[2t+8],b[2t+9]).
struct Tables {
    ulonglong2 b1frag[S_STEPS][32];
    ulonglong2 b2frag[S_STEPS][32];
    ull        w3frag[S_STEPS][32];
    float4     b1quad[S_STEPS][4];
    float4     b2quad[S_STEPS][4];
    float2     b3v[S_STEPS];
};
__device__ Tables g_tab;
__device__ float g_c1[3];   // loc1, exp(-ls1), -ls1 - 0.5*log(2pi)

__device__ __forceinline__ uint32_t packbf(float lo, float hi) {
    __nv_bfloat162 t = __floats2bfloat162_rn(lo, hi);
    return *reinterpret_cast<uint32_t*>(&t);
}

// relu on a packed bf16x2 (max against +0 in both halves)
__device__ __forceinline__ uint32_t relubf2(uint32_t v) {
    uint32_t r;
    asm("max.bf16x2 %0, %1, %2;" : "=r"(r) : "r"(v), "r"(0u));
    return r;
}

// One LDS.128 -> four b32 destinations (no struct lvalue churn).
__device__ __forceinline__ void lds128(const void* p, uint32_t& r0, uint32_t& r1,
                                       uint32_t& r2, uint32_t& r3) {
    uint32_t addr = (uint32_t)__cvta_generic_to_shared(p);
    asm("ld.shared.v4.b32 {%0,%1,%2,%3}, [%4];"
        : "=r"(r0), "=r"(r1), "=r"(r2), "=r"(r3) : "r"(addr));
}
__device__ __forceinline__ void lds64(const void* p, uint32_t& r0, uint32_t& r1) {
    uint32_t addr = (uint32_t)__cvta_generic_to_shared(p);
    asm("ld.shared.v2.b32 {%0,%1}, [%2];" : "=r"(r0), "=r"(r1) : "r"(addr));
}

__global__ void precompute_kernel(
    const float* __restrict__ n1_b1, const float* __restrict__ n1_w2,
    const float* __restrict__ n1_b2, const float* __restrict__ n1_w3,
    const float* __restrict__ n1_b3,
    const float* __restrict__ w1, const float* __restrict__ b1,
    const float* __restrict__ w2, const float* __restrict__ b2,
    const float* __restrict__ w3, const float* __restrict__ b3) {
    const int tid = threadIdx.x;

    // W1/W2 fragments (both halves) + W3 fragment (half 0)
    for (int idx = tid; idx < S_STEPS * 32; idx += blockDim.x) {
        int s = idx >> 5, l = idx & 31;
        int gid = l >> 2, tig = l & 3;
        int k0 = 2 * tig;
        const float* w1r0 = w1 + (s * 16 + gid) * 16;        // half0 n=gid
        const float* w1r1 = w1 + (s * 16 + gid + 8) * 16;    // half1 n=gid+8
        const float* w2r0 = w2 + (s * 16 + gid) * 16;
        const float* w2r1 = w2 + (s * 16 + gid + 8) * 16;
        ulonglong2 f1, f2;
        f1.x = (ull)packbf(w1r0[k0], w1r0[k0 + 1]) | ((ull)packbf(w1r0[k0 + 8], w1r0[k0 + 9]) << 32);
        f1.y = (ull)packbf(w1r1[k0], w1r1[k0 + 1]) | ((ull)packbf(w1r1[k0 + 8], w1r1[k0 + 9]) << 32);
        f2.x = (ull)packbf(w2r0[k0], w2r0[k0 + 1]) | ((ull)packbf(w2r0[k0 + 8], w2r0[k0 + 9]) << 32);
        f2.y = (ull)packbf(w2r1[k0], w2r1[k0 + 1]) | ((ull)packbf(w2r1[k0 + 8], w2r1[k0 + 9]) << 32);
        g_tab.b1frag[s][l] = f1;
        g_tab.b2frag[s][l] = f2;

        float r0 = 0.f, r1 = 0.f, r2 = 0.f, r3 = 0.f;
        if (gid == 0) { const float* w3r = w3 + s * 32;      // loc row
            r0 = w3r[k0]; r1 = w3r[k0 + 1]; r2 = w3r[k0 + 8]; r3 = w3r[k0 + 9]; }
        else if (gid == 1) { const float* w3r = w3 + s * 32 + 16;   // ls row
            r0 = w3r[k0]; r1 = w3r[k0 + 1]; r2 = w3r[k0 + 8]; r3 = w3r[k0 + 9]; }
        g_tab.w3frag[s][l] = (ull)packbf(r0, r1) | ((ull)packbf(r2, r3) << 32);
    }
    // bias quads + b3
    for (int idx = tid; idx < S_STEPS * 4; idx += blockDim.x) {
        int s = idx >> 2, t = idx & 3;
        g_tab.b1quad[s][t] = make_float4(b1[s * 16 + 2 * t], b1[s * 16 + 2 * t + 1],
                                         b1[s * 16 + 2 * t + 8], b1[s * 16 + 2 * t + 9]);
        g_tab.b2quad[s][t] = make_float4(b2[s * 16 + 2 * t], b2[s * 16 + 2 * t + 1],
                                         b2[s * 16 + 2 * t + 8], b2[s * 16 + 2 * t + 9]);
    }
    for (int s = tid; s < S_STEPS; s += blockDim.x)
        g_tab.b3v[s] = make_float2(b3[2 * s], b3[2 * s + 1]);

    // first-channel head (input is zeros -> launch constant)
    if (tid == 0) {
        float h1[16], h2[16];
        #pragma unroll
        for (int i = 0; i < 16; i++) h1[i] = fmaxf(n1_b1[i], 0.f);
        #pragma unroll
        for (int o = 0; o < 16; o++) {
            float a = n1_b2[o];
            #pragma unroll
            for (int p = 0; p < 16; p++) a += n1_w2[o * 16 + p] * h1[p];
            h2[o] = fmaxf(a, 0.f);
        }
        float loc = n1_b3[0], ls = n1_b3[1];
        #pragma unroll
        for (int p = 0; p < 16; p++) {
            loc += n1_w3[p] * h2[p];
            ls  += n1_w3[16 + p] * h2[p];
        }
        g_c1[0] = loc;
        g_c1[1] = expf(-ls);
        g_c1[2] = -ls - HALF_LOG_2PI;
    }
}

// m16n8k16 bf16 MMA, C accumulated in place (bias pre-loaded into d0..d3).
__device__ __forceinline__ void mma16816(
    float& d0, float& d1, float& d2, float& d3,
    uint32_t a0, uint32_t a1, uint32_t a2, uint32_t a3,
    uint32_t b0, uint32_t b1) {
    asm("mma.sync.aligned.m16n8k16.row.col.f32.bf16.bf16.f32 "
        "{%0,%1,%2,%3}, {%4,%5,%6,%7}, {%8,%9}, {%0,%1,%2,%3};"
        : "+f"(d0), "+f"(d1), "+f"(d2), "+f"(d3)
        : "r"(a0), "r"(a1), "r"(a2), "r"(a3), "r"(b0), "r"(b1));
}

#define SM_BYTES ((int)sizeof(Tables))

__global__ __launch_bounds__(TPB) void spatial_mma_kernel(
    const float* __restrict__ samples, float* __restrict__ out) {
    extern __shared__ char smem[];
    Tables* tab = reinterpret_cast<Tables*>(smem);
    const int tid = threadIdx.x;
    const int lane = tid & 31;
    const int wid = tid >> 5;
    const int gid = lane >> 2;    // 0..7  : D/A row group
    const int tig = lane & 3;     // 0..3  : column group

    // Stage the fragment tables into shared memory (coalesced ull copy).
    {
        const ull* src = reinterpret_cast<const ull*>(&g_tab);
        ull* dst = reinterpret_cast<ull*>(smem);
        for (int i = tid; i < SM_BYTES / 8; i += TPB) dst[i] = src[i];
    }
    __syncthreads();

    const float loc1 = g_c1[0], inv1 = g_c1[1], c1 = g_c1[2];
    const int gw = blockIdx.x * (TPB / 32) + wid;    // global warp id

    for (int tile = gw; tile < NT_TILES; tile += GRID * (TPB / 32)) {
        const int pixb = tile * 16;
        const int b = pixb >> 12;
        const int hw = pixb & 4095;
        const float* base = samples + ((size_t)b * 16) * HW + hw;

        // x (f32, exact) for this thread's fragment channels, both rows.
        float xr0[4], xr1[4];
        {
            const int c0 = 2 * tig, c2 = 2 * tig + 8;
            xr0[0] = base[c0 * HW + gid];       xr0[1] = base[(c0 + 1) * HW + gid];
            xr0[2] = base[c2 * HW + gid];       xr0[3] = base[(c2 + 1) * HW + gid];
            xr1[0] = base[c0 * HW + gid + 8];   xr1[1] = base[(c0 + 1) * HW + gid + 8];
            xr1[2] = base[c2 * HW + gid + 8];   xr1[3] = base[(c2 + 1) * HW + gid + 8];
        }

        // A fragment of X (bf16).
        uint32_t ax0 = packbf(xr0[0], xr0[1]);
        uint32_t ax1 = packbf(xr1[0], xr1[1]);
        uint32_t ax2 = packbf(xr0[2], xr0[3]);
        uint32_t ax3 = packbf(xr1[2], xr1[3]);

        // First-channel log-prob; lp0/lp1 are valid on tig==0 lanes only.
        const int qbase = lane & ~3;
        float x00 = __shfl_sync(0xffffffffu, xr0[0], qbase);
        float x01 = __shfl_sync(0xffffffffu, xr1[0], qbase);
        float z0i = (x00 - loc1) * inv1;
        float z1i = (x01 - loc1) * inv1;
        float lp0 = -0.5f * z0i * z0i + c1;
        float lp1 = -0.5f * z1i * z1i + c1;

        #pragma unroll
        for (int s = 0; s < S_STEPS; s++) {
            // ---- layer 1 (bias in C) ----
            float4 bq1 = tab->b1quad[s][tig];
            float d0 = bq1.x, d1 = bq1.y, d2 = bq1.x, d3 = bq1.y;
            float e0 = bq1.z, e1 = bq1.w, e2 = bq1.z, e3 = bq1.w;
            {
                uint32_t w00, w01, w10, w11;
                lds128(&tab->b1frag[s][lane], w00, w01, w10, w11);
                mma16816(d0, d1, d2, d3, ax0, ax1, ax2, ax3, w00, w01);
                mma16816(e0, e1, e2, e3, ax0, ax1, ax2, ax3, w10, w11);
            }
            uint32_t a10 = relubf2(packbf(d0, d1));
            uint32_t a11 = relubf2(packbf(d2, d3));
            uint32_t a12 = relubf2(packbf(e0, e1));
            uint32_t a13 = relubf2(packbf(e2, e3));

            // ---- layer 2 (bias in C) ----
            float4 bq2 = tab->b2quad[s][tig];
            float f0 = bq2.x, f1 = bq2.y, f2 = bq2.x, f3 = bq2.y;
            float g0 = bq2.z, g1 = bq2.w, g2 = bq2.z, g3 = bq2.w;
            {
                uint32_t w00, w01, w10, w11;
                lds128(&tab->b2frag[s][lane], w00, w01, w10, w11);
                mma16816(f0, f1, f2, f3, a10, a11, a12, a13, w00, w01);
                mma16816(g0, g1, g2, g3, a10, a11, a12, a13, w10, w11);
            }
            uint32_t a20 = relubf2(packbf(f0, f1));
            uint32_t a21 = relubf2(packbf(f2, f3));
            uint32_t a22 = relubf2(packbf(g0, g1));
            uint32_t a23 = relubf2(packbf(g2, g3));

            // ---- layer 3 as MMA: cols 0,1 of D = (loc, ls).  On tig==0:
            // d0=loc(pix gid), d1=ls(pix gid), d2=loc(pix gid+8), d3=ls(...).
            float2 b3p = tab->b3v[s];
            float p0 = b3p.x, p1 = b3p.y, p2 = b3p.x, p3 = b3p.y;
            {
                uint32_t w0, w1v;
                lds64(&tab->w3frag[s][lane], w0, w1v);
                mma16816(p0, p1, p2, p3, a20, a21, a22, a23, w0, w1v);
            }

            // target x[s+1] (exact f32) from its owner lane
            const int ch = s + 1;
            const int tig_o = (ch & 7) >> 1;
            const int ridx = ((ch >= 8) ? 2 : 0) + (ch & 1);
            float xs0 = __shfl_sync(0xffffffffu, xr0[ridx], qbase | tig_o);
            float xs1 = __shfl_sync(0xffffffffu, xr1[ridx], qbase | tig_o);

            // log-prob update (all lanes compute; only tig==0 values are real)
            float za = (xs0 - p0) * __expf(-p1);
            float zb = (xs1 - p2) * __expf(-p3);
            lp0 += -0.5f * za * za - p1 - HALF_LOG_2PI;
            lp1 += -0.5f * zb * zb - p3 - HALF_LOG_2PI;
        }

        if (tig == 0) {
            out[pixb + gid] = lp0;
            out[pixb + gid + 8] = lp1;
        }
    }
}

extern "C" void kernel_launch(void* const* d_in, const int* in_sizes, int n_in,
                              void* d_out, int out_size) {
    const float* samples = (const float*)d_in[0];
    // d_in[1] = n1_w1 (unused: multiplies a zeros input)
    const float* n1_b1 = (const float*)d_in[2];
    const float* n1_w2 = (const float*)d_in[3];
    const float* n1_b2 = (const float*)d_in[4];
    const float* n1_w3 = (const float*)d_in[5];
    const float* n1_b3 = (const float*)d_in[6];
    const float* w1 = (const float*)d_in[7];
    const float* b1 = (const float*)d_in[8];
    const float* w2 = (const float*)d_in[9];
    const float* b2 = (const float*)d_in[10];
    const float* w3 = (const float*)d_in[11];
    const float* b3 = (const float*)d_in[12];
    float* out = (float*)d_out;

    precompute_kernel<<<1, 256>>>(n1_b1, n1_w2, n1_b2, n1_w3, n1_b3,
                                  w1, b1, w2, b2, w3, b3);
    spatial_mma_kernel<<<GRID, TPB, SM_BYTES>>>(samples, out);
}

// round 17
// speedup vs baseline: 2.8811x; 1.1001x over previous
#include <cuda_runtime.h>
#include <cuda_bf16.h>
#include <cstdint>

// Problem constants
#define S_STEPS 15
#define HW 4096
#define NPIX (64 * 4096)
#define NT_PAIRS 8192         // NPIX / 32 pixels per warp (two 16-pixel tiles)
#define TPB 128
#define GRID 2048             // 8192 warps -> exactly one tile-pair per warp
#define HALF_LOG_2PI 0.918938533204672741780329736406f

typedef unsigned long long ull;

// ---------------- precomputed fragment tables (built on device) -------------
// B-fragment for mma.sync.m16n8k16.row.col (validated R11-R14):
//   lane (gid=lane>>2, tig=lane&3), output n = gid + 8*half:
//     b0 = { W[n][2tig],   W[n][2tig+1] },  b1 = { W[n][2tig+8], W[n][2tig+9] }
// b1frag/b2frag: both halves per lane as ulonglong2 (one LDS.128).
// w3b3: .x = layer-3 B fragment (half 0: n=0 loc row, n=1 ls row, else 0),
//       .y = (b3[s][0], b3[s][1]) as two f32 bit patterns (same for all lanes)
//       -> one LDS.128 covers layer-3 weights AND bias.
// b1quad/b2quad: per-tig bias float4 (b[2t], b[2t+1], b[2t+8], b[2t+9]).
struct Tables {
    ulonglong2 b1frag[S_STEPS][32];
    ulonglong2 b2frag[S_STEPS][32];
    ulonglong2 w3b3[S_STEPS][32];
    float4     b1quad[S_STEPS][4];
    float4     b2quad[S_STEPS][4];
};
__device__ Tables g_tab;
__device__ float g_c1[3];   // loc1, exp(-ls1), -ls1 - 0.5*log(2pi)

__device__ __forceinline__ uint32_t packbf(float lo, float hi) {
    __nv_bfloat162 t = __floats2bfloat162_rn(lo, hi);
    return *reinterpret_cast<uint32_t*>(&t);
}

// relu on a packed bf16x2 (max against +0 in both halves)
__device__ __forceinline__ uint32_t relubf2(uint32_t v) {
    uint32_t r;
    asm("max.bf16x2 %0, %1, %2;" : "=r"(r) : "r"(v), "r"(0u));
    return r;
}

// One LDS.128 -> four b32 destinations (no struct lvalue churn).
__device__ __forceinline__ void lds128(const void* p, uint32_t& r0, uint32_t& r1,
                                       uint32_t& r2, uint32_t& r3) {
    uint32_t addr = (uint32_t)__cvta_generic_to_shared(p);
    asm("ld.shared.v4.b32 {%0,%1,%2,%3}, [%4];"
        : "=r"(r0), "=r"(r1), "=r"(r2), "=r"(r3) : "r"(addr));
}

__global__ void precompute_kernel(
    const float* __restrict__ n1_b1, const float* __restrict__ n1_w2,
    const float* __restrict__ n1_b2, const float* __restrict__ n1_w3,
    const float* __restrict__ n1_b3,
    const float* __restrict__ w1, const float* __restrict__ b1,
    const float* __restrict__ w2, const float* __restrict__ b2,
    const float* __restrict__ w3, const float* __restrict__ b3) {
    const int tid = threadIdx.x;

    // W1/W2 fragments (both halves) + layer-3 fragment-with-bias
    for (int idx = tid; idx < S_STEPS * 32; idx += blockDim.x) {
        int s = idx >> 5, l = idx & 31;
        int gid = l >> 2, tig = l & 3;
        int k0 = 2 * tig;
        const float* w1r0 = w1 + (s * 16 + gid) * 16;
        const float* w1r1 = w1 + (s * 16 + gid + 8) * 16;
        const float* w2r0 = w2 + (s * 16 + gid) * 16;
        const float* w2r1 = w2 + (s * 16 + gid + 8) * 16;
        ulonglong2 f1, f2;
        f1.x = (ull)packbf(w1r0[k0], w1r0[k0 + 1]) | ((ull)packbf(w1r0[k0 + 8], w1r0[k0 + 9]) << 32);
        f1.y = (ull)packbf(w1r1[k0], w1r1[k0 + 1]) | ((ull)packbf(w1r1[k0 + 8], w1r1[k0 + 9]) << 32);
        f2.x = (ull)packbf(w2r0[k0], w2r0[k0 + 1]) | ((ull)packbf(w2r0[k0 + 8], w2r0[k0 + 9]) << 32);
        f2.y = (ull)packbf(w2r1[k0], w2r1[k0 + 1]) | ((ull)packbf(w2r1[k0 + 8], w2r1[k0 + 9]) << 32);
        g_tab.b1frag[s][l] = f1;
        g_tab.b2frag[s][l] = f2;

        float r0 = 0.f, r1 = 0.f, r2 = 0.f, r3 = 0.f;
        if (gid == 0) { const float* w3r = w3 + s * 32;            // loc row
            r0 = w3r[k0]; r1 = w3r[k0 + 1]; r2 = w3r[k0 + 8]; r3 = w3r[k0 + 9]; }
        else if (gid == 1) { const float* w3r = w3 + s * 32 + 16;  // ls row
            r0 = w3r[k0]; r1 = w3r[k0 + 1]; r2 = w3r[k0 + 8]; r3 = w3r[k0 + 9]; }
        ulonglong2 wf;
        wf.x = (ull)packbf(r0, r1) | ((ull)packbf(r2, r3) << 32);
        wf.y = (ull)__float_as_uint(b3[2 * s]) |
               ((ull)__float_as_uint(b3[2 * s + 1]) << 32);
        g_tab.w3b3[s][l] = wf;
    }
    // bias quads
    for (int idx = tid; idx < S_STEPS * 4; idx += blockDim.x) {
        int s = idx >> 2, t = idx & 3;
        g_tab.b1quad[s][t] = make_float4(b1[s * 16 + 2 * t], b1[s * 16 + 2 * t + 1],
                                         b1[s * 16 + 2 * t + 8], b1[s * 16 + 2 * t + 9]);
        g_tab.b2quad[s][t] = make_float4(b2[s * 16 + 2 * t], b2[s * 16 + 2 * t + 1],
                                         b2[s * 16 + 2 * t + 8], b2[s * 16 + 2 * t + 9]);
    }

    // first-channel head (input is zeros -> launch constant)
    if (tid == 0) {
        float h1[16], h2[16];
        #pragma unroll
        for (int i = 0; i < 16; i++) h1[i] = fmaxf(n1_b1[i], 0.f);
        #pragma unroll
        for (int o = 0; o < 16; o++) {
            float a = n1_b2[o];
            #pragma unroll
            for (int p = 0; p < 16; p++) a += n1_w2[o * 16 + p] * h1[p];
            h2[o] = fmaxf(a, 0.f);
        }
        float loc = n1_b3[0], ls = n1_b3[1];
        #pragma unroll
        for (int p = 0; p < 16; p++) {
            loc += n1_w3[p] * h2[p];
            ls  += n1_w3[16 + p] * h2[p];
        }
        g_c1[0] = loc;
        g_c1[1] = expf(-ls);
        g_c1[2] = -ls - HALF_LOG_2PI;
    }
}

// m16n8k16 bf16 MMA, C accumulated in place (bias pre-loaded into d0..d3).
__device__ __forceinline__ void mma16816(
    float& d0, float& d1, float& d2, float& d3,
    uint32_t a0, uint32_t a1, uint32_t a2, uint32_t a3,
    uint32_t b0, uint32_t b1) {
    asm("mma.sync.aligned.m16n8k16.row.col.f32.bf16.bf16.f32 "
        "{%0,%1,%2,%3}, {%4,%5,%6,%7}, {%8,%9}, {%0,%1,%2,%3};"
        : "+f"(d0), "+f"(d1), "+f"(d2), "+f"(d3)
        : "r"(a0), "r"(a1), "r"(a2), "r"(a3), "r"(b0), "r"(b1));
}

#define SM_BYTES ((int)sizeof(Tables))

__global__ __launch_bounds__(TPB) void spatial_mma_kernel(
    const float* __restrict__ samples, float* __restrict__ out) {
    extern __shared__ char smem[];
    Tables* tab = reinterpret_cast<Tables*>(smem);
    const int tid = threadIdx.x;
    const int lane = tid & 31;
    const int wid = tid >> 5;
    const int gid = lane >> 2;    // 0..7  : D/A row group
    const int tig = lane & 3;     // 0..3  : column group

    // Stage the fragment tables into shared memory (coalesced ull copy).
    {
        const ull* src = reinterpret_cast<const ull*>(&g_tab);
        ull* dst = reinterpret_cast<ull*>(smem);
        for (int i = tid; i < SM_BYTES / 8; i += TPB) dst[i] = src[i];
    }
    __syncthreads();

    const float loc1 = g_c1[0], inv1 = g_c1[1], c1 = g_c1[2];
    const int gw = blockIdx.x * (TPB / 32) + wid;    // global warp id
    const int qbase = lane & ~3;

    for (int pair = gw; pair < NT_PAIRS; pair += GRID * (TPB / 32)) {
        const int pixb = pair * 32;          // 32 pixels: two 16-pixel tiles
        const int b = pixb >> 12;
        const int hw = pixb & 4095;
        const float* base = samples + ((size_t)b * 16) * HW + hw;

        // Per-tile x fragments (f32 exact) + bf16 A fragments.
        float xr0[2][4], xr1[2][4];
        uint32_t ax[2][4];
        float lp0[2], lp1[2];
        #pragma unroll
        for (int t = 0; t < 2; t++) {
            const float* bt = base + t * 16;
            const int c0 = 2 * tig, c2 = 2 * tig + 8;
            xr0[t][0] = bt[c0 * HW + gid];     xr0[t][1] = bt[(c0 + 1) * HW + gid];
            xr0[t][2] = bt[c2 * HW + gid];     xr0[t][3] = bt[(c2 + 1) * HW + gid];
            xr1[t][0] = bt[c0 * HW + gid + 8]; xr1[t][1] = bt[(c0 + 1) * HW + gid + 8];
            xr1[t][2] = bt[c2 * HW + gid + 8]; xr1[t][3] = bt[(c2 + 1) * HW + gid + 8];
            ax[t][0] = packbf(xr0[t][0], xr0[t][1]);
            ax[t][1] = packbf(xr1[t][0], xr1[t][1]);
            ax[t][2] = packbf(xr0[t][2], xr0[t][3]);
            ax[t][3] = packbf(xr1[t][2], xr1[t][3]);
            float x00 = __shfl_sync(0xffffffffu, xr0[t][0], qbase);
            float x01 = __shfl_sync(0xffffffffu, xr1[t][0], qbase);
            float z0i = (x00 - loc1) * inv1;
            float z1i = (x01 - loc1) * inv1;
            lp0[t] = -0.5f * z0i * z0i + c1;
            lp1[t] = -0.5f * z1i * z1i + c1;
        }

        #pragma unroll
        for (int s = 0; s < S_STEPS; s++) {
            // ---- layer 1: one weight load feeds both tiles ----
            float4 bq1 = tab->b1quad[s][tig];
            uint32_t w00, w01, w10, w11;
            lds128(&tab->b1frag[s][lane], w00, w01, w10, w11);
            uint32_t a1[2][4];
            #pragma unroll
            for (int t = 0; t < 2; t++) {
                float d0 = bq1.x, d1 = bq1.y, d2 = bq1.x, d3 = bq1.y;
                float e0 = bq1.z, e1 = bq1.w, e2 = bq1.z, e3 = bq1.w;
                mma16816(d0, d1, d2, d3, ax[t][0], ax[t][1], ax[t][2], ax[t][3], w00, w01);
                mma16816(e0, e1, e2, e3, ax[t][0], ax[t][1], ax[t][2], ax[t][3], w10, w11);
                a1[t][0] = relubf2(packbf(d0, d1));
                a1[t][1] = relubf2(packbf(d2, d3));
                a1[t][2] = relubf2(packbf(e0, e1));
                a1[t][3] = relubf2(packbf(e2, e3));
            }

            // ---- layer 2 ----
            float4 bq2 = tab->b2quad[s][tig];
            lds128(&tab->b2frag[s][lane], w00, w01, w10, w11);
            uint32_t a2[2][4];
            #pragma unroll
            for (int t = 0; t < 2; t++) {
                float f0 = bq2.x, f1 = bq2.y, f2 = bq2.x, f3 = bq2.y;
                float g0 = bq2.z, g1 = bq2.w, g2 = bq2.z, g3 = bq2.w;
                mma16816(f0, f1, f2, f3, a1[t][0], a1[t][1], a1[t][2], a1[t][3], w00, w01);
                mma16816(g0, g1, g2, g3, a1[t][0], a1[t][1], a1[t][2], a1[t][3], w10, w11);
                a2[t][0] = relubf2(packbf(f0, f1));
                a2[t][1] = relubf2(packbf(f2, f3));
                a2[t][2] = relubf2(packbf(g0, g1));
                a2[t][3] = relubf2(packbf(g2, g3));
            }

            // ---- layer 3 as MMA (weights+bias in one LDS.128) ----
            uint32_t w3a, w3b, b3xu, b3yu;
            lds128(&tab->w3b3[s][lane], w3a, w3b, b3xu, b3yu);
            const float b3x = __uint_as_float(b3xu);
            const float b3y = __uint_as_float(b3yu);

            const int ch = s + 1;
            const int tig_o = (ch & 7) >> 1;
            const int ridx = ((ch >= 8) ? 2 : 0) + (ch & 1);

            #pragma unroll
            for (int t = 0; t < 2; t++) {
                float p0 = b3x, p1 = b3y, p2 = b3x, p3 = b3y;
                mma16816(p0, p1, p2, p3, a2[t][0], a2[t][1], a2[t][2], a2[t][3], w3a, w3b);
                // target x[s+1] (exact f32) from its owner lane
                float xs0 = __shfl_sync(0xffffffffu, xr0[t][ridx], qbase | tig_o);
                float xs1 = __shfl_sync(0xffffffffu, xr1[t][ridx], qbase | tig_o);
                // log-prob update (all lanes compute; tig==0 values are real)
                float za = (xs0 - p0) * __expf(-p1);
                float zb = (xs1 - p2) * __expf(-p3);
                lp0[t] += -0.5f * za * za - p1 - HALF_LOG_2PI;
                lp1[t] += -0.5f * zb * zb - p3 - HALF_LOG_2PI;
            }
        }

        if (tig == 0) {
            out[pixb + gid] = lp0[0];
            out[pixb + gid + 8] = lp1[0];
            out[pixb + 16 + gid] = lp0[1];
            out[pixb + 16 + gid + 8] = lp1[1];
        }
    }
}

extern "C" void kernel_launch(void* const* d_in, const int* in_sizes, int n_in,
                              void* d_out, int out_size) {
    const float* samples = (const float*)d_in[0];
    // d_in[1] = n1_w1 (unused: multiplies a zeros input)
    const float* n1_b1 = (const float*)d_in[2];
    const float* n1_w2 = (const float*)d_in[3];
    const float* n1_b2 = (const float*)d_in[4];
    const float* n1_w3 = (const float*)d_in[5];
    const float* n1_b3 = (const float*)d_in[6];
    const float* w1 = (const float*)d_in[7];
    const float* b1 = (const float*)d_in[8];
    const float* w2 = (const float*)d_in[9];
    const float* b2 = (const float*)d_in[10];
    const float* w3 = (const float*)d_in[11];
    const float* b3 = (const float*)d_in[12];
    float* out = (float*)d_out;

    precompute_kernel<<<1, 256>>>(n1_b1, n1_w2, n1_b2, n1_w3, n1_b3,
                                  w1, b1, w2, b2, w3, b3);
    spatial_mma_kernel<<<GRID, TPB, SM_BYTES>>>(samples, out);
}